// round 2
// baseline (speedup 1.0000x reference)
#include <cuda_runtime.h>
#include <math.h>
#include <stdint.h>

// ---------------------------------------------------------------------------
// Scratch (device globals; no allocations allowed)
// ---------------------------------------------------------------------------
#define BT_MAX 4096
__device__ float g_q   [BT_MAX * 2048];  // [token][16][128] (rope+rmsnorm+scale, in-place)
__device__ float g_kraw[BT_MAX * 1024];  // raw k projection [token][8][128]
__device__ float g_k   [BT_MAX * 1024];  // shifted+rope+rmsnorm k
__device__ float g_v   [BT_MAX * 1024];  // v (+ ve gate, in-place)
__device__ float g_y   [BT_MAX * 2048];  // attention output [token][16][128]
__device__ float g_vgate[BT_MAX * 8];
__device__ float g_agate[BT_MAX * 16];

// ---------------------------------------------------------------------------
// SGEMM: C[M,N] = A[M,K] @ B[K,N], row-major, M,N multiples of 128, K mult of 8
// 128x128 tile, BK=8, 256 threads, 8x8 micro-tile, float4 everywhere.
// Optional epilogue scale = (1 + scale_ptr[0]).
// ---------------------------------------------------------------------------
__global__ __launch_bounds__(256)
void sgemm_kernel(int M, int N, int K,
                  const float* __restrict__ A,
                  const float* __restrict__ B,
                  float* __restrict__ C,
                  const float* __restrict__ scale_ptr)
{
    constexpr int BM = 128, BN = 128, BK = 8, TM = 8, TN = 8;
    __shared__ float As[BK][BM];
    __shared__ float Bs[BK][BN];

    const int tid = threadIdx.x;
    const int bcol = blockIdx.x, brow = blockIdx.y;

    A += (size_t)brow * BM * K;
    B += (size_t)bcol * BN;
    C += (size_t)brow * BM * N + (size_t)bcol * BN;

    const int arow = tid >> 1;           // 0..127
    const int acol = (tid & 1) * 4;      // 0 or 4
    const int brw  = tid >> 5;           // 0..7
    const int bcl  = (tid & 31) * 4;     // 0..124

    const int trow = (tid >> 4) * TM;    // 0..120
    const int tcol = (tid & 15) * TN;    // 0..120

    float acc[TM][TN] = {};
    for (int k0 = 0; k0 < K; k0 += BK) {
        float4 av = *(const float4*)(A + (size_t)arow * K + k0 + acol);
        As[acol + 0][arow] = av.x;
        As[acol + 1][arow] = av.y;
        As[acol + 2][arow] = av.z;
        As[acol + 3][arow] = av.w;
        *(float4*)&Bs[brw][bcl] = *(const float4*)(B + (size_t)(k0 + brw) * N + bcl);
        __syncthreads();
        #pragma unroll
        for (int kk = 0; kk < BK; kk++) {
            float4 a0 = *(const float4*)&As[kk][trow];
            float4 a1 = *(const float4*)&As[kk][trow + 4];
            float4 b0 = *(const float4*)&Bs[kk][tcol];
            float4 b1 = *(const float4*)&Bs[kk][tcol + 4];
            float ra[TM] = {a0.x,a0.y,a0.z,a0.w,a1.x,a1.y,a1.z,a1.w};
            float rb[TN] = {b0.x,b0.y,b0.z,b0.w,b1.x,b1.y,b1.z,b1.w};
            #pragma unroll
            for (int i = 0; i < TM; i++)
                #pragma unroll
                for (int j = 0; j < TN; j++)
                    acc[i][j] = fmaf(ra[i], rb[j], acc[i][j]);
        }
        __syncthreads();
    }

    float scale = scale_ptr ? (1.0f + scale_ptr[0]) : 1.0f;
    #pragma unroll
    for (int i = 0; i < TM; i++) {
        #pragma unroll
        for (int j = 0; j < TN; j += 4) {
            float4 o = { acc[i][j+0]*scale, acc[i][j+1]*scale,
                         acc[i][j+2]*scale, acc[i][j+3]*scale };
            *(float4*)(C + (size_t)(trow + i) * N + tcol + j) = o;
        }
    }
}

// ---------------------------------------------------------------------------
// Gates: ve-gate (2*sigmoid(x[:,:32] @ Wve[32,8])) and attn-gate
// (sigmoid(x[:,:12] @ Wag[12,16])). One thread per (token, output).
// ---------------------------------------------------------------------------
__global__ void gates_kernel(const float* __restrict__ x,
                             const float* __restrict__ wve,
                             const float* __restrict__ wag,
                             int BT)
{
    int idx = blockIdx.x * blockDim.x + threadIdx.x;
    if (idx >= BT * 24) return;
    int token = idx / 24, j = idx % 24;
    const float* xr = x + (size_t)token * 2048;
    if (j < 8) {
        float s = 0.f;
        #pragma unroll
        for (int c = 0; c < 32; c++) s = fmaf(xr[c], wve[c * 8 + j], s);
        g_vgate[token * 8 + j] = 2.f / (1.f + __expf(-s));
    } else {
        int hh = j - 8;
        float s = 0.f;
        #pragma unroll
        for (int c = 0; c < 12; c++) s = fmaf(xr[c], wag[c * 16 + hh], s);
        g_agate[token * 16 + hh] = 1.f / (1.f + __expf(-s));
    }
}

// v += vgate[h] * ve   (float4 over BT*1024 floats)
__global__ void v_add_ve_kernel(const float* __restrict__ ve, int BT)
{
    int i = blockIdx.x * blockDim.x + threadIdx.x;
    if (i >= BT * 256) return;
    int token = i >> 8;
    int h = (i >> 5) & 7;
    float g = g_vgate[token * 8 + h];
    float4 vv = ((float4*)g_v)[i];
    float4 e = ((const float4*)ve)[i];
    vv.x = fmaf(g, e.x, vv.x);
    vv.y = fmaf(g, e.y, vv.y);
    vv.z = fmaf(g, e.z, vv.z);
    vv.w = fmaf(g, e.w, vv.w);
    ((float4*)g_v)[i] = vv;
}

// ---------------------------------------------------------------------------
// RoPE + RMSNorm. One warp per (token, head) row of 128.
// mode 0: q in-place, scale folds in 1/sqrt(128).
// mode 1: k from g_kraw with second-half time shift (t-1, clamp per batch),
//         writes g_k.
// Lane l owns dims [4l, 4l+3]; lanes 0..15 = first half, 16..31 = second half.
// ---------------------------------------------------------------------------
__global__ void qk_prep_kernel(const float* __restrict__ cosp,
                               const float* __restrict__ sinp,
                               int mode, int T)
{
    int gid = blockIdx.x * blockDim.x + threadIdx.x;
    int row = gid >> 5;
    int lane = gid & 31;
    int nh = (mode == 0) ? 16 : 8;
    int h = row % nh;
    int token = row / nh;
    int t = token % T;
    int d0 = lane * 4;

    float4 v;
    if (mode == 0) {
        v = *(const float4*)(g_q + (size_t)row * 128 + d0);
    } else {
        int srct = (d0 < 64 || t == 0) ? token : token - 1;
        v = *(const float4*)(g_kraw + ((size_t)srct * 8 + h) * 128 + d0);
    }

    float ox = __shfl_xor_sync(0xffffffffu, v.x, 16);
    float oy = __shfl_xor_sync(0xffffffffu, v.y, 16);
    float oz = __shfl_xor_sync(0xffffffffu, v.z, 16);
    float ow = __shfl_xor_sync(0xffffffffu, v.w, 16);

    int dm = d0 & 63;
    float4 c = *(const float4*)(cosp + (size_t)t * 64 + dm);
    float4 s = *(const float4*)(sinp + (size_t)t * 64 + dm);
    float sign = (lane < 16) ? 1.f : -1.f;

    float r0 = fmaf(sign * ox, s.x, v.x * c.x);
    float r1 = fmaf(sign * oy, s.y, v.y * c.y);
    float r2 = fmaf(sign * oz, s.z, v.z * c.z);
    float r3 = fmaf(sign * ow, s.w, v.w * c.w);

    float ss = r0*r0 + r1*r1 + r2*r2 + r3*r3;
    #pragma unroll
    for (int o = 16; o; o >>= 1) ss += __shfl_xor_sync(0xffffffffu, ss, o);

    float sc = rsqrtf(ss * (1.f / 128.f) + 1.1920929e-7f);
    if (mode == 0) sc *= 0.08838834764831845f;  // 1/sqrt(HEAD_DIM)

    float4 out = { r0*sc, r1*sc, r2*sc, r3*sc };
    float* dst = (mode == 0) ? (g_q + (size_t)row * 128 + d0)
                             : (g_k + (size_t)row * 128 + d0);
    *(float4*)dst = out;
}

// ---------------------------------------------------------------------------
// Flash-style sliding-window attention. Block = (b, head, 16 consecutive q's).
// 512 threads; each warp owns one query (lane owns 4 output dims). Key tiles
// of 32 shared by all warps through smem. Online softmax.
// ---------------------------------------------------------------------------
__global__ __launch_bounds__(512)
void attn_kernel(const int* __restrict__ wsz, int T)
{
    __shared__ float4 qs[16][33];  // padded rows (33 float4)
    __shared__ float4 ks[32][33];
    __shared__ float4 vs[32][32];
    __shared__ float  ps[16][32];

    int h = blockIdx.y, b = blockIdx.z;
    int t0 = blockIdx.x * 16;
    int tid = threadIdx.x;
    int warp = tid >> 5, lane = tid & 31;
    int kvh = h >> 1;
    int W = wsz[0];

    {   // load q tile: 512 float4 loads, one per thread
        int qi = tid >> 5, d4 = tid & 31;
        int tq = t0 + qi;
        float4 qv = {0,0,0,0};
        if (tq < T)
            qv = *(const float4*)(g_q + (((size_t)(b * T + tq)) * 16 + h) * 128 + d4 * 4);
        qs[qi][d4] = qv;
    }

    int t = t0 + warp;
    bool active = (t < T);
    float m = -INFINITY, l = 0.f;
    float4 acc = {0,0,0,0};

    int jstart = max(0, t0 - W) & ~31;
    int jend = min(t0 + 15, T - 1);

    for (int j0 = jstart; j0 <= jend; j0 += 32) {
        __syncthreads();
        for (int i = tid; i < 32 * 32; i += 512) {
            int jj = i >> 5, d4 = i & 31;
            int j = j0 + jj;
            float4 kv = {0,0,0,0}, vv = {0,0,0,0};
            if (j < T) {
                size_t base = (((size_t)(b * T + j)) * 8 + kvh) * 128 + d4 * 4;
                kv = *(const float4*)(g_k + base);
                vv = *(const float4*)(g_v + base);
            }
            ks[jj][d4] = kv;
            vs[jj][d4] = vv;
        }
        __syncthreads();

        int j = j0 + lane;
        int dist = t - j;
        bool valid = active && (dist >= 0) && (dist <= W) && (j < T);

        float sum = 0.f;
        #pragma unroll
        for (int d4 = 0; d4 < 32; d4++) {
            float4 kk = ks[lane][d4];
            float4 qq = qs[warp][d4];
            sum = fmaf(kk.x, qq.x, sum);
            sum = fmaf(kk.y, qq.y, sum);
            sum = fmaf(kk.z, qq.z, sum);
            sum = fmaf(kk.w, qq.w, sum);
        }
        float sco = valid ? sum : -INFINITY;

        float tm = sco;
        #pragma unroll
        for (int o = 16; o; o >>= 1)
            tm = fmaxf(tm, __shfl_xor_sync(0xffffffffu, tm, o));
        if (tm == -INFINITY) continue;   // warp-uniform; whole tile masked

        float mnew = fmaxf(m, tm);
        float corr = __expf(m - mnew);   // 0 when m = -inf
        float p = valid ? __expf(sco - mnew) : 0.f;
        ps[warp][lane] = p;
        float rs = p;
        #pragma unroll
        for (int o = 16; o; o >>= 1) rs += __shfl_xor_sync(0xffffffffu, rs, o);
        l = l * corr + rs;
        acc.x *= corr; acc.y *= corr; acc.z *= corr; acc.w *= corr;
        m = mnew;
        __syncwarp();

        #pragma unroll
        for (int jj = 0; jj < 32; jj++) {
            float pj = ps[warp][jj];
            float4 vv = vs[jj][lane];
            acc.x = fmaf(pj, vv.x, acc.x);
            acc.y = fmaf(pj, vv.y, acc.y);
            acc.z = fmaf(pj, vv.z, acc.z);
            acc.w = fmaf(pj, vv.w, acc.w);
        }
    }

    if (active) {
        float sc = (1.f / l) * g_agate[(size_t)(b * T + t) * 16 + h];
        float4 o = { acc.x * sc, acc.y * sc, acc.z * sc, acc.w * sc };
        *(float4*)(g_y + (((size_t)(b * T + t)) * 16 + h) * 128 + lane * 4) = o;
    }
}

// ---------------------------------------------------------------------------
// Launch
// ---------------------------------------------------------------------------
extern "C" void kernel_launch(void* const* d_in, const int* in_sizes, int n_in,
                              void* d_out, int out_size)
{
    const float* x     = (const float*)d_in[0];
    const float* ve    = (const float*)d_in[1];
    const float* cosp  = (const float*)d_in[2];
    const float* sinp  = (const float*)d_in[3];
    const float* wq    = (const float*)d_in[4];
    const float* wk    = (const float*)d_in[5];
    const float* wv    = (const float*)d_in[6];
    const float* wproj = (const float*)d_in[7];
    const float* wveg  = (const float*)d_in[8];
    const float* wag   = (const float*)d_in[9];
    const float* pscal = (const float*)d_in[10];
    const int*   wsz   = (const int*)d_in[11];

    const int C  = 2048;
    const int BT = in_sizes[0] / C;       // B*T
    const int T  = in_sizes[2] / 64;      // cos is (1,T,1,64)
    const int B  = BT / T;

    float *pq, *pkraw, *pv, *py;
    cudaGetSymbolAddress((void**)&pq,    g_q);
    cudaGetSymbolAddress((void**)&pkraw, g_kraw);
    cudaGetSymbolAddress((void**)&pv,    g_v);
    cudaGetSymbolAddress((void**)&py,    g_y);

    // 1-3. QKV projections
    sgemm_kernel<<<dim3(2048/128, BT/128), 256>>>(BT, 2048, C, x, wq, pq, nullptr);
    sgemm_kernel<<<dim3(1024/128, BT/128), 256>>>(BT, 1024, C, x, wk, pkraw, nullptr);
    sgemm_kernel<<<dim3(1024/128, BT/128), 256>>>(BT, 1024, C, x, wv, pv, nullptr);

    // 4. gates, 5. v += gate*ve
    gates_kernel<<<(BT * 24 + 255) / 256, 256>>>(x, wveg, wag, BT);
    v_add_ve_kernel<<<(BT * 256 + 255) / 256, 256>>>(ve, BT);

    // 6-7. q / k: rope + rmsnorm (+shift for k, +1/sqrt(hd) for q)
    qk_prep_kernel<<<(BT * 16 * 32) / 256, 256>>>(cosp, sinp, 0, T);
    qk_prep_kernel<<<(BT * 8 * 32) / 256, 256>>>(cosp, sinp, 1, T);

    // 8. sliding-window attention (+attn gate)
    attn_kernel<<<dim3((T + 15) / 16, 16, B), 512>>>(wsz, T);

    // 9. output projection with (1 + proj_scalar)
    sgemm_kernel<<<dim3(2048/128, BT/128), 256>>>(BT, 2048, C, py, wproj,
                                                  (float*)d_out, pscal);
}

// round 3
// speedup vs baseline: 1.0003x; 1.0003x over previous
#include <cuda_runtime.h>
#include <math.h>
#include <stdint.h>

// ---------------------------------------------------------------------------
// Scratch (device globals; no allocations allowed)
// ---------------------------------------------------------------------------
#define BT_MAX 4096
__device__ float g_q   [BT_MAX * 2048];  // [token][16][128] (rope+rmsnorm+scale, in-place)
__device__ float g_kraw[BT_MAX * 1024];  // raw k projection [token][8][128]
__device__ float g_k   [BT_MAX * 1024];  // shifted+rope+rmsnorm k
__device__ float g_v   [BT_MAX * 1024];  // v (+ ve gate, in-place)
__device__ float g_y   [BT_MAX * 2048];  // attention output [token][16][128]
__device__ float g_vgate[BT_MAX * 8];
__device__ float g_agate[BT_MAX * 16];

// ---------------------------------------------------------------------------
// SGEMM: C[M,N] = A[M,K] @ B[K,N], row-major, M,N multiples of 128, K mult of 8
// 128x128 tile, BK=8, 256 threads, 8x8 micro-tile, float4 everywhere.
// Optional epilogue scale = (1 + scale_ptr[0]).
// ---------------------------------------------------------------------------
__global__ __launch_bounds__(256)
void sgemm_kernel(int M, int N, int K,
                  const float* __restrict__ A,
                  const float* __restrict__ B,
                  float* __restrict__ C,
                  const float* __restrict__ scale_ptr)
{
    constexpr int BM = 128, BN = 128, BK = 8, TM = 8, TN = 8;
    __shared__ float As[BK][BM];
    __shared__ float Bs[BK][BN];

    const int tid = threadIdx.x;
    const int bcol = blockIdx.x, brow = blockIdx.y;

    A += (size_t)brow * BM * K;
    B += (size_t)bcol * BN;
    C += (size_t)brow * BM * N + (size_t)bcol * BN;

    const int arow = tid >> 1;           // 0..127
    const int acol = (tid & 1) * 4;      // 0 or 4
    const int brw  = tid >> 5;           // 0..7
    const int bcl  = (tid & 31) * 4;     // 0..124

    const int trow = (tid >> 4) * TM;    // 0..120
    const int tcol = (tid & 15) * TN;    // 0..120

    float acc[TM][TN] = {};
    for (int k0 = 0; k0 < K; k0 += BK) {
        float4 av = *(const float4*)(A + (size_t)arow * K + k0 + acol);
        As[acol + 0][arow] = av.x;
        As[acol + 1][arow] = av.y;
        As[acol + 2][arow] = av.z;
        As[acol + 3][arow] = av.w;
        *(float4*)&Bs[brw][bcl] = *(const float4*)(B + (size_t)(k0 + brw) * N + bcl);
        __syncthreads();
        #pragma unroll
        for (int kk = 0; kk < BK; kk++) {
            float4 a0 = *(const float4*)&As[kk][trow];
            float4 a1 = *(const float4*)&As[kk][trow + 4];
            float4 b0 = *(const float4*)&Bs[kk][tcol];
            float4 b1 = *(const float4*)&Bs[kk][tcol + 4];
            float ra[TM] = {a0.x,a0.y,a0.z,a0.w,a1.x,a1.y,a1.z,a1.w};
            float rb[TN] = {b0.x,b0.y,b0.z,b0.w,b1.x,b1.y,b1.z,b1.w};
            #pragma unroll
            for (int i = 0; i < TM; i++)
                #pragma unroll
                for (int j = 0; j < TN; j++)
                    acc[i][j] = fmaf(ra[i], rb[j], acc[i][j]);
        }
        __syncthreads();
    }

    float scale = scale_ptr ? (1.0f + scale_ptr[0]) : 1.0f;
    #pragma unroll
    for (int i = 0; i < TM; i++) {
        #pragma unroll
        for (int j = 0; j < TN; j += 4) {
            float4 o = { acc[i][j+0]*scale, acc[i][j+1]*scale,
                         acc[i][j+2]*scale, acc[i][j+3]*scale };
            *(float4*)(C + (size_t)(trow + i) * N + tcol + j) = o;
        }
    }
}

// ---------------------------------------------------------------------------
// Gates: ve-gate (2*sigmoid(x[:,:32] @ Wve[32,8])) and attn-gate
// (sigmoid(x[:,:12] @ Wag[12,16])). One thread per (token, output).
// ---------------------------------------------------------------------------
__global__ void gates_kernel(const float* __restrict__ x,
                             const float* __restrict__ wve,
                             const float* __restrict__ wag,
                             int BT)
{
    int idx = blockIdx.x * blockDim.x + threadIdx.x;
    if (idx >= BT * 24) return;
    int token = idx / 24, j = idx % 24;
    const float* xr = x + (size_t)token * 2048;
    if (j < 8) {
        float s = 0.f;
        #pragma unroll
        for (int c = 0; c < 32; c++) s = fmaf(xr[c], wve[c * 8 + j], s);
        g_vgate[token * 8 + j] = 2.f / (1.f + __expf(-s));
    } else {
        int hh = j - 8;
        float s = 0.f;
        #pragma unroll
        for (int c = 0; c < 12; c++) s = fmaf(xr[c], wag[c * 16 + hh], s);
        g_agate[token * 16 + hh] = 1.f / (1.f + __expf(-s));
    }
}

// v += vgate[h] * ve   (float4 over BT*1024 floats)
__global__ void v_add_ve_kernel(const float* __restrict__ ve, int BT)
{
    int i = blockIdx.x * blockDim.x + threadIdx.x;
    if (i >= BT * 256) return;
    int token = i >> 8;
    int h = (i >> 5) & 7;
    float g = g_vgate[token * 8 + h];
    float4 vv = ((float4*)g_v)[i];
    float4 e = ((const float4*)ve)[i];
    vv.x = fmaf(g, e.x, vv.x);
    vv.y = fmaf(g, e.y, vv.y);
    vv.z = fmaf(g, e.z, vv.z);
    vv.w = fmaf(g, e.w, vv.w);
    ((float4*)g_v)[i] = vv;
}

// ---------------------------------------------------------------------------
// RoPE + RMSNorm. One warp per (token, head) row of 128.
// mode 0: q in-place, scale folds in 1/sqrt(128).
// mode 1: k from g_kraw with second-half time shift (t-1, clamp per batch),
//         writes g_k.
// Lane l owns dims [4l, 4l+3]; lanes 0..15 = first half, 16..31 = second half.
// ---------------------------------------------------------------------------
__global__ void qk_prep_kernel(const float* __restrict__ cosp,
                               const float* __restrict__ sinp,
                               int mode, int T)
{
    int gid = blockIdx.x * blockDim.x + threadIdx.x;
    int row = gid >> 5;
    int lane = gid & 31;
    int nh = (mode == 0) ? 16 : 8;
    int h = row % nh;
    int token = row / nh;
    int t = token % T;
    int d0 = lane * 4;

    float4 v;
    if (mode == 0) {
        v = *(const float4*)(g_q + (size_t)row * 128 + d0);
    } else {
        int srct = (d0 < 64 || t == 0) ? token : token - 1;
        v = *(const float4*)(g_kraw + ((size_t)srct * 8 + h) * 128 + d0);
    }

    float ox = __shfl_xor_sync(0xffffffffu, v.x, 16);
    float oy = __shfl_xor_sync(0xffffffffu, v.y, 16);
    float oz = __shfl_xor_sync(0xffffffffu, v.z, 16);
    float ow = __shfl_xor_sync(0xffffffffu, v.w, 16);

    int dm = d0 & 63;
    float4 c = *(const float4*)(cosp + (size_t)t * 64 + dm);
    float4 s = *(const float4*)(sinp + (size_t)t * 64 + dm);
    float sign = (lane < 16) ? 1.f : -1.f;

    float r0 = fmaf(sign * ox, s.x, v.x * c.x);
    float r1 = fmaf(sign * oy, s.y, v.y * c.y);
    float r2 = fmaf(sign * oz, s.z, v.z * c.z);
    float r3 = fmaf(sign * ow, s.w, v.w * c.w);

    float ss = r0*r0 + r1*r1 + r2*r2 + r3*r3;
    #pragma unroll
    for (int o = 16; o; o >>= 1) ss += __shfl_xor_sync(0xffffffffu, ss, o);

    float sc = rsqrtf(ss * (1.f / 128.f) + 1.1920929e-7f);
    if (mode == 0) sc *= 0.08838834764831845f;  // 1/sqrt(HEAD_DIM)

    float4 out = { r0*sc, r1*sc, r2*sc, r3*sc };
    float* dst = (mode == 0) ? (g_q + (size_t)row * 128 + d0)
                             : (g_k + (size_t)row * 128 + d0);
    *(float4*)dst = out;
}

// ---------------------------------------------------------------------------
// Flash-style sliding-window attention. Block = (b, head, 16 consecutive q's).
// 512 threads; each warp owns one query (lane owns 4 output dims). Key tiles
// of 32 shared by all warps through smem. Online softmax.
// ---------------------------------------------------------------------------
__global__ __launch_bounds__(512)
void attn_kernel(const int* __restrict__ wsz, int T)
{
    __shared__ float4 qs[16][33];  // padded rows (33 float4)
    __shared__ float4 ks[32][33];
    __shared__ float4 vs[32][32];
    __shared__ float  ps[16][32];

    int h = blockIdx.y, b = blockIdx.z;
    int t0 = blockIdx.x * 16;
    int tid = threadIdx.x;
    int warp = tid >> 5, lane = tid & 31;
    int kvh = h >> 1;
    int W = wsz[0];

    {   // load q tile: 512 float4 loads, one per thread
        int qi = tid >> 5, d4 = tid & 31;
        int tq = t0 + qi;
        float4 qv = {0,0,0,0};
        if (tq < T)
            qv = *(const float4*)(g_q + (((size_t)(b * T + tq)) * 16 + h) * 128 + d4 * 4);
        qs[qi][d4] = qv;
    }

    int t = t0 + warp;
    bool active = (t < T);
    float m = -INFINITY, l = 0.f;
    float4 acc = {0,0,0,0};

    int jstart = max(0, t0 - W) & ~31;
    int jend = min(t0 + 15, T - 1);

    for (int j0 = jstart; j0 <= jend; j0 += 32) {
        __syncthreads();
        for (int i = tid; i < 32 * 32; i += 512) {
            int jj = i >> 5, d4 = i & 31;
            int j = j0 + jj;
            float4 kv = {0,0,0,0}, vv = {0,0,0,0};
            if (j < T) {
                size_t base = (((size_t)(b * T + j)) * 8 + kvh) * 128 + d4 * 4;
                kv = *(const float4*)(g_k + base);
                vv = *(const float4*)(g_v + base);
            }
            ks[jj][d4] = kv;
            vs[jj][d4] = vv;
        }
        __syncthreads();

        int j = j0 + lane;
        int dist = t - j;
        bool valid = active && (dist >= 0) && (dist <= W) && (j < T);

        float sum = 0.f;
        #pragma unroll
        for (int d4 = 0; d4 < 32; d4++) {
            float4 kk = ks[lane][d4];
            float4 qq = qs[warp][d4];
            sum = fmaf(kk.x, qq.x, sum);
            sum = fmaf(kk.y, qq.y, sum);
            sum = fmaf(kk.z, qq.z, sum);
            sum = fmaf(kk.w, qq.w, sum);
        }
        float sco = valid ? sum : -INFINITY;

        float tm = sco;
        #pragma unroll
        for (int o = 16; o; o >>= 1)
            tm = fmaxf(tm, __shfl_xor_sync(0xffffffffu, tm, o));
        if (tm == -INFINITY) continue;   // warp-uniform; whole tile masked

        float mnew = fmaxf(m, tm);
        float corr = __expf(m - mnew);   // 0 when m = -inf
        float p = valid ? __expf(sco - mnew) : 0.f;
        ps[warp][lane] = p;
        float rs = p;
        #pragma unroll
        for (int o = 16; o; o >>= 1) rs += __shfl_xor_sync(0xffffffffu, rs, o);
        l = l * corr + rs;
        acc.x *= corr; acc.y *= corr; acc.z *= corr; acc.w *= corr;
        m = mnew;
        __syncwarp();

        #pragma unroll
        for (int jj = 0; jj < 32; jj++) {
            float pj = ps[warp][jj];
            float4 vv = vs[jj][lane];
            acc.x = fmaf(pj, vv.x, acc.x);
            acc.y = fmaf(pj, vv.y, acc.y);
            acc.z = fmaf(pj, vv.z, acc.z);
            acc.w = fmaf(pj, vv.w, acc.w);
        }
    }

    if (active) {
        float sc = (1.f / l) * g_agate[(size_t)(b * T + t) * 16 + h];
        float4 o = { acc.x * sc, acc.y * sc, acc.z * sc, acc.w * sc };
        *(float4*)(g_y + (((size_t)(b * T + t)) * 16 + h) * 128 + lane * 4) = o;
    }
}

// ---------------------------------------------------------------------------
// Launch
// ---------------------------------------------------------------------------
extern "C" void kernel_launch(void* const* d_in, const int* in_sizes, int n_in,
                              void* d_out, int out_size)
{
    const float* x     = (const float*)d_in[0];
    const float* ve    = (const float*)d_in[1];
    const float* cosp  = (const float*)d_in[2];
    const float* sinp  = (const float*)d_in[3];
    const float* wq    = (const float*)d_in[4];
    const float* wk    = (const float*)d_in[5];
    const float* wv    = (const float*)d_in[6];
    const float* wproj = (const float*)d_in[7];
    const float* wveg  = (const float*)d_in[8];
    const float* wag   = (const float*)d_in[9];
    const float* pscal = (const float*)d_in[10];
    const int*   wsz   = (const int*)d_in[11];

    const int C  = 2048;
    const int BT = in_sizes[0] / C;       // B*T
    const int T  = in_sizes[2] / 64;      // cos is (1,T,1,64)
    const int B  = BT / T;

    float *pq, *pkraw, *pv, *py;
    cudaGetSymbolAddress((void**)&pq,    g_q);
    cudaGetSymbolAddress((void**)&pkraw, g_kraw);
    cudaGetSymbolAddress((void**)&pv,    g_v);
    cudaGetSymbolAddress((void**)&py,    g_y);

    // 1-3. QKV projections
    sgemm_kernel<<<dim3(2048/128, BT/128), 256>>>(BT, 2048, C, x, wq, pq, nullptr);
    sgemm_kernel<<<dim3(1024/128, BT/128), 256>>>(BT, 1024, C, x, wk, pkraw, nullptr);
    sgemm_kernel<<<dim3(1024/128, BT/128), 256>>>(BT, 1024, C, x, wv, pv, nullptr);

    // 4. gates, 5. v += gate*ve
    gates_kernel<<<(BT * 24 + 255) / 256, 256>>>(x, wveg, wag, BT);
    v_add_ve_kernel<<<(BT * 256 + 255) / 256, 256>>>(ve, BT);

    // 6-7. q / k: rope + rmsnorm (+shift for k, +1/sqrt(hd) for q)
    qk_prep_kernel<<<(BT * 16 * 32) / 256, 256>>>(cosp, sinp, 0, T);
    qk_prep_kernel<<<(BT * 8 * 32) / 256, 256>>>(cosp, sinp, 1, T);

    // 8. sliding-window attention (+attn gate)
    attn_kernel<<<dim3((T + 15) / 16, 16, B), 512>>>(wsz, T);

    // 9. output projection with (1 + proj_scalar)
    sgemm_kernel<<<dim3(2048/128, BT/128), 256>>>(BT, 2048, C, py, wproj,
                                                  (float*)d_out, pscal);
}